// round 4
// baseline (speedup 1.0000x reference)
#include <cuda_runtime.h>

// Output == input (reference returns x reshaped; everything else is dead code).
// Pure copy: 302 MB read + 302 MB write.
//
// n floats = 75,497,472 ; n float4 = 18,874,368 = 9216 blocks * 256 threads * 8.
// Fully unrolled, loop-free, 32-bit indexing. 8 independent 16B streaming loads
// front-batched (MLP=8) then 8 streaming stores. No guards, no tail.

__global__ void __launch_bounds__(256) copy8_kernel(const float4* __restrict__ src,
                                                    float4* __restrict__ dst) {
    unsigned i = blockIdx.x * 2048u + threadIdx.x;  // 2048 = 256 threads * 8 chunks
    float4 v0 = __ldcs(src + i);
    float4 v1 = __ldcs(src + i + 256u);
    float4 v2 = __ldcs(src + i + 512u);
    float4 v3 = __ldcs(src + i + 768u);
    float4 v4 = __ldcs(src + i + 1024u);
    float4 v5 = __ldcs(src + i + 1280u);
    float4 v6 = __ldcs(src + i + 1536u);
    float4 v7 = __ldcs(src + i + 1792u);
    __stcs(dst + i,          v0);
    __stcs(dst + i + 256u,   v1);
    __stcs(dst + i + 512u,   v2);
    __stcs(dst + i + 768u,   v3);
    __stcs(dst + i + 1024u,  v4);
    __stcs(dst + i + 1280u,  v5);
    __stcs(dst + i + 1536u,  v6);
    __stcs(dst + i + 1792u,  v7);
}

// Generic fallback (only used if sizes ever differ from the expected shape).
__global__ void copy_generic(const float* __restrict__ src, float* __restrict__ dst,
                             long long n) {
    long long i = (long long)blockIdx.x * blockDim.x + threadIdx.x;
    long long stride = (long long)gridDim.x * blockDim.x;
    for (; i < n; i += stride) dst[i] = src[i];
}

extern "C" void kernel_launch(void* const* d_in, const int* in_sizes, int n_in,
                              void* d_out, int out_size) {
    (void)n_in;
    long long n = out_size;
    if (n == 75497472LL && in_sizes[0] >= out_size) {
        copy8_kernel<<<9216, 256>>>((const float4*)d_in[0], (float4*)d_out);
    } else {
        long long nn = n;
        if ((long long)in_sizes[0] < nn) nn = in_sizes[0];
        int blocks = (int)((nn + 255) / 256);
        if (blocks > 147456) blocks = 147456;
        copy_generic<<<blocks, 256>>>((const float*)d_in[0], (float*)d_out, nn);
    }
}